// round 7
// baseline (speedup 1.0000x reference)
#include <cuda_runtime.h>
#include <cuda_bf16.h>
#include <mma.h>
#include <cstdint>
#include <cstdio>

using namespace nvcuda;

#define NN 100000
#define NE 500000
#define MPAD 100096          // 782 * 128, padded row count for guard-free GEMM
#define FMAX 768

// ---------------- scratch (device globals: allowed; no cudaMalloc) ----------
__device__ __align__(16) float g_bufA[(size_t)MPAD * FMAX];
__device__ __align__(16) float g_bufB[(size_t)MPAD * FMAX];
__device__ float g_dinv[NN];
__device__ int   g_cnt[NN];
__device__ int   g_fill[NN];
__device__ int   g_rowptr[NN + 1];
__device__ int   g_col[NE];
__device__ float g_w[NE];
__device__ int   g_is64;

// ---------------- edge-index dtype detection --------------------------------
__global__ void detect_k(const long long* __restrict__ p) {
    if (threadIdx.x == 0 && blockIdx.x == 0) {
        int ok = 1;
        for (int i = 0; i < 256; i++) {
            long long v = p[i];
            if (v < 0 || v >= (long long)NN) { ok = 0; break; }
        }
        g_is64 = ok;
    }
}

__device__ __forceinline__ int edge_at(const void* p, int idx) {
    if (g_is64) return (int)((const long long*)p)[idx];
    return ((const int*)p)[idx];
}

// ---------------- CSR build --------------------------------------------------
__global__ void zero_k() {
    int i = blockIdx.x * blockDim.x + threadIdx.x;
    if (i < NN) { g_cnt[i] = 0; g_fill[i] = 0; }
}

__global__ void count_k(const void* __restrict__ ei) {
    int e = blockIdx.x * blockDim.x + threadIdx.x;
    if (e < NE) {
        int d = edge_at(ei, NE + e);   // dst row
        atomicAdd(&g_cnt[d], 1);
    }
}

__global__ void dinv_k() {
    int i = blockIdx.x * blockDim.x + threadIdx.x;
    if (i < NN) g_dinv[i] = rsqrtf((float)g_cnt[i] + 1.0f);  // +1 self-loop
}

__global__ void scan_k() {
    __shared__ int ssum[1024];
    const int T = 1024;
    int t = threadIdx.x;
    int chunk = (NN + T - 1) / T;
    int start = t * chunk;
    int end   = start + chunk; if (end > NN) end = NN;
    int s = 0;
    for (int i = start; i < end && i < NN; i++) s += g_cnt[i];
    ssum[t] = s;
    __syncthreads();
    for (int off = 1; off < T; off <<= 1) {
        int v = ssum[t];
        int add = (t >= off) ? ssum[t - off] : 0;
        __syncthreads();
        ssum[t] = v + add;
        __syncthreads();
    }
    int run = (t > 0) ? ssum[t - 1] : 0;
    for (int i = start; i < end && i < NN; i++) { g_rowptr[i] = run; run += g_cnt[i]; }
    if (t == T - 1) g_rowptr[NN] = ssum[T - 1];
}

__global__ void fill_k(const void* __restrict__ ei) {
    int e = blockIdx.x * blockDim.x + threadIdx.x;
    if (e < NE) {
        int s = edge_at(ei, e);
        int d = edge_at(ei, NE + e);
        int pos = g_rowptr[d] + atomicAdd(&g_fill[d], 1);
        g_col[pos] = s;
        g_w[pos]   = g_dinv[s] * g_dinv[d];
    }
}

// ---------------- exact GELU -------------------------------------------------
__device__ __forceinline__ float geluf(float x) {
    return 0.5f * x * (1.0f + erff(x * 0.7071067811865475f));
}

// ---------------- pull-mode aggregation (one warp per node, no atomics) ------
template <int V>   // V float4 per lane; F = 128*V
__global__ void agg_kernel(const float* __restrict__ X, float* __restrict__ Y,
                           const float* __restrict__ bias, int doGelu) {
    const int F = 128 * V;
    int gw   = (blockIdx.x * blockDim.x + threadIdx.x) >> 5;
    int lane = threadIdx.x & 31;
    int nw   = (gridDim.x * blockDim.x) >> 5;
    for (int i = gw; i < NN; i += nw) {
        float d  = g_dinv[i];
        float sw = d * d;
        const float4* xi = (const float4*)(X + (size_t)i * F);
        float4 acc[V];
#pragma unroll
        for (int v = 0; v < V; v++) {
            float4 t = xi[lane + 32 * v];
            acc[v].x = t.x * sw; acc[v].y = t.y * sw;
            acc[v].z = t.z * sw; acc[v].w = t.w * sw;
        }
        if (bias) {
#pragma unroll
            for (int v = 0; v < V; v++) {
                float4 b = ((const float4*)bias)[lane + 32 * v];
                acc[v].x += b.x; acc[v].y += b.y; acc[v].z += b.z; acc[v].w += b.w;
            }
        }
        int e0 = g_rowptr[i], e1 = g_rowptr[i + 1];
        for (int e = e0; e < e1; e++) {
            int   s  = __ldg(&g_col[e]);
            float we = __ldg(&g_w[e]);
            const float4* xs = (const float4*)(X + (size_t)s * F);
#pragma unroll
            for (int v = 0; v < V; v++) {
                float4 t = xs[lane + 32 * v];
                acc[v].x += we * t.x; acc[v].y += we * t.y;
                acc[v].z += we * t.z; acc[v].w += we * t.w;
            }
        }
        if (doGelu) {
#pragma unroll
            for (int v = 0; v < V; v++) {
                acc[v].x = geluf(acc[v].x); acc[v].y = geluf(acc[v].y);
                acc[v].z = geluf(acc[v].z); acc[v].w = geluf(acc[v].w);
            }
        }
        float4* yi = (float4*)(Y + (size_t)i * F);
#pragma unroll
        for (int v = 0; v < V; v++) yi[lane + 32 * v] = acc[v];
    }
}

// ---------------- cp.async helpers -------------------------------------------
__device__ __forceinline__ void cp_async16(uint32_t saddr, const void* gptr) {
    asm volatile("cp.async.cg.shared.global [%0], [%1], 16;\n"
                 :: "r"(saddr), "l"(gptr));
}
__device__ __forceinline__ void cp_commit() {
    asm volatile("cp.async.commit_group;\n");
}
template <int n>
__device__ __forceinline__ void cp_wait() {
    asm volatile("cp.async.wait_group %0;\n" :: "n"(n));
}

// ---------------- TF32 WMMA GEMM, 2-stage cp.async pipeline ------------------
// C[MPAD,Nn] = A[MPAD,K] @ B[K,Nn], row-major, guard-free (M padded, Nn%128==0,
// K%32==0). Dynamic smem: 2 stages of (As 128x36 + Bs 32x132) = 70656 B.
// Epilogue bias+GELU staging buffer aliases stage-0 As.
#define BMg 128
#define BNg 128
#define BKg 32
#define AS_STRIDE (BKg + 4)              // 36
#define BS_STRIDE (BNg + 4)              // 132
#define AS_FLOATS (BMg * AS_STRIDE)      // 4608
#define BS_FLOATS (BKg * BS_STRIDE)      // 4224
#define STAGE_FLOATS (AS_FLOATS + BS_FLOATS)
#define GEMM_SMEM_BYTES (2 * STAGE_FLOATS * 4)   // 70656

__global__ __launch_bounds__(256) void gemm_tf32(const float* __restrict__ A,
                                                 const float* __restrict__ B,
                                                 float* __restrict__ C,
                                                 int K, int Nn,
                                                 const float* __restrict__ bias,
                                                 int doGelu) {
    extern __shared__ float smem[];
    float* As[2] = { smem,                smem + STAGE_FLOATS };
    float* Bs[2] = { smem + AS_FLOATS,    smem + STAGE_FLOATS + AS_FLOATS };

    int bm = blockIdx.y, bn = blockIdx.x;
    int tid  = threadIdx.x;
    int wid  = tid >> 5;
    int lane = tid & 31;
    int warpM = wid >> 2;   // 0..1 (64 rows each)
    int warpN = wid & 3;    // 0..3 (32 cols each)

    wmma::fragment<wmma::accumulator, 16, 16, 8, float> acc[4][2];
#pragma unroll
    for (int i = 0; i < 4; i++)
#pragma unroll
        for (int j = 0; j < 2; j++) wmma::fill_fragment(acc[i][j], 0.0f);

    const float* Ab = A + (size_t)bm * BMg * K;
    const float* Bb = B + (size_t)bn * BNg;

    // per-thread tile slot coordinates (fixed)
    int arA[4], acA[4], arB[4], acB[4];
    uint32_t sA[2][4], sB[2][4];
#pragma unroll
    for (int i = 0; i < 4; i++) {
        int f = tid + i * 256;
        arA[i] = f >> 3;  acA[i] = (f & 7) << 2;
        arB[i] = f >> 5;  acB[i] = (f & 31) << 2;
#pragma unroll
        for (int st = 0; st < 2; st++) {
            sA[st][i] = (uint32_t)__cvta_generic_to_shared(
                As[st] + arA[i] * AS_STRIDE + acA[i]);
            sB[st][i] = (uint32_t)__cvta_generic_to_shared(
                Bs[st] + arB[i] * BS_STRIDE + acB[i]);
        }
    }

    int ktiles = K / BKg;
    // prefetch tile 0 into stage 0
#pragma unroll
    for (int i = 0; i < 4; i++) {
        cp_async16(sA[0][i], Ab + (size_t)arA[i] * K + acA[i]);
        cp_async16(sB[0][i], Bb + (size_t)arB[i] * Nn + acB[i]);
    }
    cp_commit();

    for (int kt = 0; kt < ktiles; kt++) {
        int cur = kt & 1;
        // issue prefetch for tile kt+1 into the other stage
        if (kt + 1 < ktiles) {
            int nxt = (kt + 1) & 1;
            int k0  = (kt + 1) * BKg;
#pragma unroll
            for (int i = 0; i < 4; i++) {
                cp_async16(sA[nxt][i], Ab + (size_t)arA[i] * K + k0 + acA[i]);
                cp_async16(sB[nxt][i], Bb + (size_t)(k0 + arB[i]) * Nn + acB[i]);
            }
            cp_commit();
            cp_wait<1>();   // tile kt resident; kt+1 still in flight
        } else {
            cp_wait<0>();
        }
        __syncthreads();

#pragma unroll
        for (int kk = 0; kk < BKg / 8; kk++) {
            wmma::fragment<wmma::matrix_a, 16, 16, 8, wmma::precision::tf32, wmma::row_major> af[4];
            wmma::fragment<wmma::matrix_b, 16, 16, 8, wmma::precision::tf32, wmma::row_major> bf[2];
#pragma unroll
            for (int i = 0; i < 4; i++) {
                wmma::load_matrix_sync(af[i],
                    As[cur] + (warpM * 64 + i * 16) * AS_STRIDE + kk * 8, AS_STRIDE);
#pragma unroll
                for (int t = 0; t < af[i].num_elements; t++)
                    af[i].x[t] = wmma::__float_to_tf32(af[i].x[t]);
            }
#pragma unroll
            for (int j = 0; j < 2; j++) {
                wmma::load_matrix_sync(bf[j],
                    Bs[cur] + (kk * 8) * BS_STRIDE + warpN * 32 + j * 16, BS_STRIDE);
#pragma unroll
                for (int t = 0; t < bf[j].num_elements; t++)
                    bf[j].x[t] = wmma::__float_to_tf32(bf[j].x[t]);
            }
#pragma unroll
            for (int i = 0; i < 4; i++)
#pragma unroll
                for (int j = 0; j < 2; j++)
                    wmma::mma_sync(acc[i][j], af[i], bf[j], acc[i][j]);
        }
        __syncthreads();
    }

    // ---- epilogue ----
    if (!bias && !doGelu) {
#pragma unroll
        for (int i = 0; i < 4; i++)
#pragma unroll
            for (int j = 0; j < 2; j++) {
                float* Cp = C + (size_t)(bm * BMg + warpM * 64 + i * 16) * Nn
                              + bn * BNg + warpN * 32 + j * 16;
                wmma::store_matrix_sync(Cp, acc[i][j], Nn, wmma::mem_row_major);
            }
        return;
    }
    // fused bias+gelu: per-warp 16x16 stage aliasing stage-0 As smem (320 floats/warp)
    float* St = smem + wid * 16 * 20;
    int r  = lane >> 1;
    int c0 = (lane & 1) * 8;
#pragma unroll
    for (int i = 0; i < 4; i++)
#pragma unroll
        for (int j = 0; j < 2; j++) {
            wmma::store_matrix_sync(St, acc[i][j], 20, wmma::mem_row_major);
            __syncwarp();
            int colbase = bn * BNg + warpN * 32 + j * 16;
            int row     = bm * BMg + warpM * 64 + i * 16 + r;
            float v[8];
#pragma unroll
            for (int t = 0; t < 8; t++) {
                float val = St[r * 20 + c0 + t];
                if (bias) val += __ldg(&bias[colbase + c0 + t]);
                if (doGelu) val = geluf(val);
                v[t] = val;
            }
            float4* dst = (float4*)(C + (size_t)row * Nn + colbase + c0);
            dst[0] = make_float4(v[0], v[1], v[2], v[3]);
            dst[1] = make_float4(v[4], v[5], v[6], v[7]);
            __syncwarp();
        }
}

// ---------------- launch -----------------------------------------------------
extern "C" void kernel_launch(void* const* d_in, const int* in_sizes, int n_in,
                              void* d_out, int out_size) {
    const float* x  = (const float*)d_in[0];
    const void*  ei = d_in[1];
    const float* W1 = (const float*)d_in[2];
    const float* b1 = (const float*)d_in[3];
    const float* W2 = (const float*)d_in[4];
    const float* b2 = (const float*)d_in[5];
    const float* W3 = (const float*)d_in[6];
    const float* b3 = (const float*)d_in[7];
    const float* W4 = (const float*)d_in[8];
    const float* b4 = (const float*)d_in[9];
    float* out = (float*)d_out;

    float *bufA, *bufB;
    cudaGetSymbolAddress((void**)&bufA, g_bufA);
    cudaGetSymbolAddress((void**)&bufB, g_bufB);

    static int smem_cfg = 0;
    if (!smem_cfg) {
        cudaFuncSetAttribute(gemm_tf32,
            cudaFuncAttributeMaxDynamicSharedMemorySize, GEMM_SMEM_BYTES);
        smem_cfg = 1;
    }

    const int TB = 256;
    const int nblk   = (NN + TB - 1) / TB;
    const int eblk   = (NE + TB - 1) / TB;
    const int aggblk = 2048;

    // ---- CSR build (per launch; deterministic) ----
    detect_k<<<1, 32>>>((const long long*)ei);
    zero_k<<<nblk, TB>>>();
    count_k<<<eblk, TB>>>(ei);
    dinv_k<<<nblk, TB>>>();
    scan_k<<<1, 1024>>>();
    fill_k<<<eblk, TB>>>(ei);

    // ---- layer 1: aggregate(F=128) -> GEMM(128->512)+bias+gelu ----
    agg_kernel<1><<<aggblk, TB>>>(x, bufA, nullptr, 0);
    gemm_tf32<<<dim3(4, MPAD / 128), 256, GEMM_SMEM_BYTES>>>(bufA, W1, bufB, 128, 512, b1, 1);

    // ---- layer 2: aggregate(F=512) -> GEMM(512->768)+bias+gelu ----
    agg_kernel<4><<<aggblk, TB>>>(bufB, bufA, nullptr, 0);
    gemm_tf32<<<dim3(6, MPAD / 128), 256, GEMM_SMEM_BYTES>>>(bufA, W2, bufB, 512, 768, b2, 1);

    // ---- layer 3: GEMM(768->512) -> aggregate(F=512, +b3, gelu) ----
    gemm_tf32<<<dim3(4, MPAD / 128), 256, GEMM_SMEM_BYTES>>>(bufB, W3, bufA, 768, 512, nullptr, 0);
    agg_kernel<4><<<aggblk, TB>>>(bufA, bufB, b3, 1);

    // ---- layer 4: GEMM(512->128) -> aggregate(F=128, +b4) -> out ----
    gemm_tf32<<<dim3(1, MPAD / 128), 256, GEMM_SMEM_BYTES>>>(bufB, W4, bufA, 512, 128, nullptr, 0);
    agg_kernel<1><<<aggblk, TB>>>(bufA, out, b4, 0);
}